// round 8
// baseline (speedup 1.0000x reference)
#include <cuda_runtime.h>

#define BB   2
#define NN   512
#define OBJ  320
#define GEO  6
#define LANG 256
#define HID  256
#define ROWS (BB*NN)   // 1024

#define C2 0.3989423f
#define C4 -0.0664904f
#define TWO_C2 0.79788456f

typedef unsigned long long u64;

__device__ __forceinline__ u64 pk2(float lo, float hi) {
    u64 r; asm("mov.b64 %0, {%1, %2};" : "=l"(r) : "f"(lo), "f"(hi)); return r;
}
__device__ __forceinline__ void upk2(float& lo, float& hi, u64 v) {
    asm("mov.b64 {%0, %1}, %2;" : "=f"(lo), "=f"(hi) : "l"(v));
}
__device__ __forceinline__ u64 ffma2(u64 a, u64 b, u64 c) {
    u64 d; asm("fma.rn.f32x2 %0, %1, %2, %3;" : "=l"(d) : "l"(a), "l"(b), "l"(c)); return d;
}

// L2-resident scratch
__device__ float g_emb[ROWS*OBJ];     // normalized embeddings
__device__ float g_FAt[HID*ROWS];     // [h][i]: 2*c2*W2[h]*hi[i,h]
__device__ float g_FBt[HID*ROWS];     // [h][j]: hj[j,h]
__device__ float g_Si [2*ROWS];       // per-h-half partials
__device__ float g_Sj [2*ROWS];
__device__ float g_sc [ROWS*NN];      // cross scores
__device__ float g_pw [ROWS*NN];      // softmax pair weights

// ============ K1: norm + lang + projections + features + Si/Sj partials ============
// grid 128 = 64 row-tiles (16 rows) x 2 h-halves (128 h each). 256 threads.
__global__ void __launch_bounds__(256) k_proj(const float* __restrict__ emb_raw,
                                              const float* __restrict__ geom,
                                              const float* __restrict__ utter,
                                              const float* __restrict__ W1,
                                              const float* __restrict__ b1,
                                              const float* __restrict__ W2) {
    __shared__ float e_s[16][OBJ+1];               // 20.5 KB (padded)
    __shared__ __align__(16) float2 ep[OBJ][8];    // 20 KB row-pairs
    __shared__ __align__(16) float2 gp[GEO][8];
    __shared__ float ls[LANG];
    __shared__ float redl[8];
    __shared__ float red_si[8][8], red_sj[8][8];

    int bx = blockIdx.x;
    int rowtile = bx >> 1, half = bx & 1;
    int row0 = rowtile * 16;
    int h0 = half * 128;
    int b = row0 >> 9;
    int t = threadIdx.x;
    int lane = t & 31, warp = t >> 5;
    int hh = t & 127, rp = t >> 7;                 // h-index, row-pair group
    int h = h0 + hh;

    // stage raw emb rows + utterance
    for (int idx = t; idx < 16*OBJ; idx += 256) {
        int r = idx / OBJ, d = idx - r*OBJ;
        e_s[r][d] = emb_raw[(row0 + r)*OBJ + d];
    }
    float lv = utter[b*LANG + t];
    {
        float ss = lv*lv;
        #pragma unroll
        for (int o = 16; o; o >>= 1) ss += __shfl_xor_sync(0xffffffffu, ss, o);
        if (lane == 0) redl[warp] = ss;
    }
    __syncthreads();

    // normalize: warp w owns rows w and w+8
    {
        #pragma unroll
        for (int rr = 0; rr < 2; rr++) {
            int r = warp + rr*8;
            float ss = 0.f;
            for (int d = lane; d < OBJ; d += 32) { float v = e_s[r][d]; ss = fmaf(v, v, ss); }
            #pragma unroll
            for (int o = 16; o; o >>= 1) ss += __shfl_xor_sync(0xffffffffu, ss, o);
            float inv = rsqrtf(ss);
            float* gdst = g_emb + (row0 + r)*OBJ;
            for (int d = lane; d < OBJ; d += 32) {
                float v = e_s[r][d] * inv;
                e_s[r][d] = v;
                if (half == 0) gdst[d] = v;
            }
        }
        float tot = 0.f;
        #pragma unroll
        for (int w = 0; w < 8; w++) tot += redl[w];
        ls[t] = lv * rsqrtf(tot);
    }
    __syncthreads();

    // build pair layouts; overlap with hl (lang projection) LDG loop
    float hlv = b1[h];
    {
        const float* Wl = W1 + (2*OBJ + GEO)*HID + h;
        #pragma unroll 4
        for (int l = 0; l < LANG; l++) hlv = fmaf(ls[l], Wl[l*HID], hlv);
    }
    for (int idx = t; idx < OBJ*8; idx += 256) {
        int d = idx >> 3, p = idx & 7;
        ep[d][p] = make_float2(e_s[2*p][d], e_s[2*p+1][d]);
    }
    if (t < GEO*8) {
        int d = t >> 3, p = t & 7;
        gp[d][p] = make_float2(geom[(row0 + 2*p)*GEO + d], geom[(row0 + 2*p + 1)*GEO + d]);
    }
    __syncthreads();

    // main projection: thread handles 4 row-pairs (rp*4 .. rp*4+3) for its h
    u64 ai[4], aj[4];
    #pragma unroll
    for (int p = 0; p < 4; p++) { ai[p] = 0ull; aj[p] = 0ull; }
    const float* Wi = W1 + h;
    const float* Wj = W1 + OBJ*HID + h;
    #pragma unroll 4
    for (int d = 0; d < OBJ; d++) {
        float wi = Wi[d*HID];
        float wj = Wj[d*HID];
        u64 wip = pk2(wi, wi), wjp = pk2(wj, wj);
        ulonglong2 E01 = *(const ulonglong2*)&ep[d][rp*4];
        ulonglong2 E23 = *(const ulonglong2*)&ep[d][rp*4 + 2];
        ai[0] = ffma2(E01.x, wip, ai[0]);  aj[0] = ffma2(E01.x, wjp, aj[0]);
        ai[1] = ffma2(E01.y, wip, ai[1]);  aj[1] = ffma2(E01.y, wjp, aj[1]);
        ai[2] = ffma2(E23.x, wip, ai[2]);  aj[2] = ffma2(E23.x, wjp, aj[2]);
        ai[3] = ffma2(E23.y, wip, ai[3]);  aj[3] = ffma2(E23.y, wjp, aj[3]);
    }
    const float* Wg = W1 + 2*OBJ*HID + h;
    #pragma unroll
    for (int g = 0; g < GEO; g++) {
        float wg = Wg[g*HID];
        u64 wgp = pk2(wg, wg), wgm = pk2(-wg, -wg);
        ulonglong2 G01 = *(const ulonglong2*)&gp[g][rp*4];
        ulonglong2 G23 = *(const ulonglong2*)&gp[g][rp*4 + 2];
        ai[0] = ffma2(G01.x, wgm, ai[0]);  aj[0] = ffma2(G01.x, wgp, aj[0]);
        ai[1] = ffma2(G01.y, wgm, ai[1]);  aj[1] = ffma2(G01.y, wgp, aj[1]);
        ai[2] = ffma2(G23.x, wgm, ai[2]);  aj[2] = ffma2(G23.x, wgp, aj[2]);
        ai[3] = ffma2(G23.y, wgm, ai[3]);  aj[3] = ffma2(G23.y, wgp, aj[3]);
    }

    // epilogue: features + per-row partial reductions
    float w2v = W2[h];
    float sir[8], sjr[8];
    #pragma unroll
    for (int p = 0; p < 4; p++) {
        int P = rp*4 + p;
        float a0, a1, j0v, j1v;
        upk2(a0, a1, ai[p]);
        upk2(j0v, j1v, aj[p]);
        float hv0 = a0 + hlv, hv1 = a1 + hlv;
        *(float2*)&g_FAt[h*ROWS + row0 + 2*P] = make_float2(TWO_C2*w2v*hv0, TWO_C2*w2v*hv1);
        *(float2*)&g_FBt[h*ROWS + row0 + 2*P] = make_float2(j0v, j1v);
        float u0 = hv0*hv0, u1 = hv1*hv1;
        sir[2*p]   = w2v * fmaf(u0, fmaf(C4, u0, C2), 0.5f*hv0);
        sir[2*p+1] = w2v * fmaf(u1, fmaf(C4, u1, C2), 0.5f*hv1);
        float v0 = j0v*j0v, v1 = j1v*j1v;
        sjr[2*p]   = w2v * fmaf(v0, fmaf(C4, v0, C2), 0.5f*j0v);
        sjr[2*p+1] = w2v * fmaf(v1, fmaf(C4, v1, C2), 0.5f*j1v);
    }
    #pragma unroll
    for (int lr = 0; lr < 8; lr++) {
        float si = sir[lr], sj = sjr[lr];
        #pragma unroll
        for (int o = 16; o; o >>= 1) {
            si += __shfl_xor_sync(0xffffffffu, si, o);
            sj += __shfl_xor_sync(0xffffffffu, sj, o);
        }
        if (lane == 0) { red_si[warp][lr] = si; red_sj[warp][lr] = sj; }
    }
    __syncthreads();
    if (t < 16) {                 // rows 0..15: Si partial
        int rpg = t >> 3, lr = t & 7;
        float v = red_si[rpg*4+0][lr] + red_si[rpg*4+1][lr]
                + red_si[rpg*4+2][lr] + red_si[rpg*4+3][lr];
        g_Si[half*ROWS + row0 + t] = v;
    } else if (t < 32) {
        int r = t - 16;
        int rpg = r >> 3, lr = r & 7;
        float v = red_sj[rpg*4+0][lr] + red_sj[rpg*4+1][lr]
                + red_sj[rpg*4+2][lr] + red_sj[rpg*4+3][lr];
        g_Sj[half*ROWS + row0 + r] = v;
    }
}

// ============ K2: cross GEMM  g_sc[i,j] = sum_h FAt[h,i]*FBt[h,j] ============
__global__ void __launch_bounds__(256) k_gemm() {
    __shared__ __align__(16) float2 Asp[16][64];   // duplicated (a,a) pairs
    __shared__ __align__(16) float  Bs [16][64];
    int t = threadIdx.x;
    int tx = t & 15, ty = t >> 4;
    int lk = t >> 4, l4 = (t & 15) * 4;
    int b  = blockIdx.z;
    int i0 = b*NN + blockIdx.y*64;
    int j0 = b*NN + blockIdx.x*64;

    const float* pa = g_FAt + lk*ROWS + i0 + l4;
    const float* pb = g_FBt + lk*ROWS + j0 + l4;

    u64 acc2[4][2];
    #pragma unroll
    for (int r = 0; r < 4; r++) { acc2[r][0] = 0ull; acc2[r][1] = 0ull; }

    float4 a4 = *(const float4*)pa;
    float4 b4 = *(const float4*)pb;

    #pragma unroll 1
    for (int ch = 0; ch < 16; ch++) {
        *(float4*)&Asp[lk][l4]     = make_float4(a4.x, a4.x, a4.y, a4.y);
        *(float4*)&Asp[lk][l4 + 2] = make_float4(a4.z, a4.z, a4.w, a4.w);
        *(float4*)&Bs[lk][l4] = b4;
        __syncthreads();
        if (ch < 15) {
            a4 = *(const float4*)(pa + (ch+1)*16*ROWS);
            b4 = *(const float4*)(pb + (ch+1)*16*ROWS);
        }
        #pragma unroll
        for (int k = 0; k < 16; k++) {
            ulonglong2 aA = *(const ulonglong2*)&Asp[k][ty*4];
            ulonglong2 aB = *(const ulonglong2*)&Asp[k][ty*4 + 2];
            ulonglong2 bP = *(const ulonglong2*)&Bs[k][tx*4];
            acc2[0][0] = ffma2(aA.x, bP.x, acc2[0][0]);
            acc2[0][1] = ffma2(aA.x, bP.y, acc2[0][1]);
            acc2[1][0] = ffma2(aA.y, bP.x, acc2[1][0]);
            acc2[1][1] = ffma2(aA.y, bP.y, acc2[1][1]);
            acc2[2][0] = ffma2(aB.x, bP.x, acc2[2][0]);
            acc2[2][1] = ffma2(aB.x, bP.y, acc2[2][1]);
            acc2[3][0] = ffma2(aB.y, bP.x, acc2[3][0]);
            acc2[3][1] = ffma2(aB.y, bP.y, acc2[3][1]);
        }
        __syncthreads();
    }

    int irow = i0 + ty*4;
    int jcol = blockIdx.x*64 + tx*4;
    #pragma unroll
    for (int r = 0; r < 4; r++) {
        float c0, c1, c2v, c3;
        upk2(c0, c1, acc2[r][0]);
        upk2(c2v, c3, acc2[r][1]);
        *(float4*)&g_sc[(irow + r)*NN + jcol] = make_float4(c0, c1, c2v, c3);
    }
}

// ============ K3: softmax + relation_scores ============
__global__ void k_soft(const float* __restrict__ b2p, float* __restrict__ out_scores) {
    int row = blockIdx.x;
    int b = row >> 9;
    int t = threadIdx.x;              // 128 threads, 4 cols each
    int lane = t & 31, warp = t >> 5;
    __shared__ float rm[4], rs[4], rss[4];

    float4 cr  = *(const float4*)&g_sc[row*NN + t*4];
    float4 j0  = *(const float4*)&g_Sj[b*NN + t*4];
    float4 j1  = *(const float4*)&g_Sj[ROWS + b*NN + t*4];
    float s0 = cr.x + j0.x + j1.x, s1 = cr.y + j0.y + j1.y;
    float s2 = cr.z + j0.z + j1.z, s3 = cr.w + j0.w + j1.w;

    float m = fmaxf(fmaxf(s0, s1), fmaxf(s2, s3));
    #pragma unroll
    for (int o = 16; o; o >>= 1) m = fmaxf(m, __shfl_xor_sync(0xffffffffu, m, o));
    if (lane == 0) rm[warp] = m;
    __syncthreads();
    m = fmaxf(fmaxf(rm[0], rm[1]), fmaxf(rm[2], rm[3]));

    float e0 = __expf(s0 - m), e1 = __expf(s1 - m), e2 = __expf(s2 - m), e3 = __expf(s3 - m);
    float se  = (e0 + e1) + (e2 + e3);
    float ses = fmaf(e0, s0, fmaf(e1, s1, fmaf(e2, s2, e3*s3)));
    #pragma unroll
    for (int o = 16; o; o >>= 1) {
        se  += __shfl_xor_sync(0xffffffffu, se,  o);
        ses += __shfl_xor_sync(0xffffffffu, ses, o);
    }
    if (lane == 0) { rs[warp] = se; rss[warp] = ses; }
    __syncthreads();
    float setot  = (rs[0]  + rs[1])  + (rs[2]  + rs[3]);
    float sestot = (rss[0] + rss[1]) + (rss[2] + rss[3]);

    float inv = __fdividef(1.f, setot);
    float4 pw = make_float4(e0*inv, e1*inv, e2*inv, e3*inv);
    *(float4*)&g_pw[row*NN + t*4] = pw;
    if (t == 0) out_scores[row] = sestot*inv + g_Si[row] + g_Si[ROWS + row] + b2p[0];
}

// ============ K4: relation_context = pw @ emb_n  (K-chunked GEMM) ============
// grid (4 d-tiles, 16 i-tiles, 2 batches) = 128 CTAs, 256 threads.
// thread: i_loc = t>>3 (32 rows), dx = t&7 -> 10 d-cols (5 float2 pairs).
// pw_s padded to 36 floats/row: 144B (16B-aligned float4 stores) AND 4-bank
// row offset so the 4 distinct i_loc reads per warp are conflict-free.
__global__ void __launch_bounds__(256) k_ctx(float* __restrict__ out_ctx) {
    __shared__ __align__(16) float e_s[32][80];    // 10 KB
    __shared__ __align__(16) float pw_s[32][36];   // 4.5 KB
    int t = threadIdx.x;
    int i_loc = t >> 3, dx = t & 7;
    int d0 = blockIdx.x * 80;
    int b  = blockIdx.z;
    int i0 = b*NN + blockIdx.y * 32;    // global row
    int dbase = dx * 10;

    u64 acc[5];
    #pragma unroll
    for (int q = 0; q < 5; q++) acc[q] = 0ull;

    // prefetch chunk 0
    float2 epre[5];
    float4 ppre;
    {
        #pragma unroll
        for (int pass = 0; pass < 5; pass++) {
            int idx = t + pass*256;          // over 1280 float2
            int jr = idx / 40, dc = idx - jr*40;
            epre[pass] = *(const float2*)&g_emb[(size_t)(b*NN + jr)*OBJ + d0 + dc*2];
        }
        int pr = t >> 3, pc = (t & 7) * 4;
        ppre = *(const float4*)&g_pw[(size_t)(i0 + pr)*NN + pc];
    }

    #pragma unroll 1
    for (int ch = 0; ch < 16; ch++) {
        {   // store prefetched chunk
            #pragma unroll
            for (int pass = 0; pass < 5; pass++) {
                int idx = t + pass*256;
                int jr = idx / 40, dc = idx - jr*40;
                *(float2*)&e_s[jr][dc*2] = epre[pass];
            }
            int pr = t >> 3, pc = (t & 7) * 4;
            *(float4*)&pw_s[pr][pc] = ppre;
        }
        __syncthreads();
        if (ch < 15) {
            int j0n = (ch + 1) * 32;
            #pragma unroll
            for (int pass = 0; pass < 5; pass++) {
                int idx = t + pass*256;
                int jr = idx / 40, dc = idx - jr*40;
                epre[pass] = *(const float2*)&g_emb[(size_t)(b*NN + j0n + jr)*OBJ + d0 + dc*2];
            }
            int pr = t >> 3, pc = (t & 7) * 4;
            ppre = *(const float4*)&g_pw[(size_t)(i0 + pr)*NN + j0n + pc];
        }
        #pragma unroll
        for (int jk = 0; jk < 32; jk++) {
            float pwv = pw_s[i_loc][jk];
            u64 pwp = pk2(pwv, pwv);
            #pragma unroll
            for (int q = 0; q < 5; q++) {
                u64 e2 = *(const u64*)&e_s[jk][dbase + 2*q];
                acc[q] = ffma2(pwp, e2, acc[q]);
            }
        }
        __syncthreads();
    }

    float* orow = out_ctx + (size_t)(i0 + i_loc)*OBJ + d0 + dbase;
    #pragma unroll
    for (int q = 0; q < 5; q++) {
        float x0, x1;
        upk2(x0, x1, acc[q]);
        *(float2*)&orow[2*q] = make_float2(x0, x1);
    }
}

extern "C" void kernel_launch(void* const* d_in, const int* in_sizes, int n_in,
                              void* d_out, int out_size) {
    (void)in_sizes; (void)n_in; (void)out_size;
    const float* emb   = (const float*)d_in[0];
    const float* geom  = (const float*)d_in[1];
    const float* utter = (const float*)d_in[2];
    const float* W1    = (const float*)d_in[3];
    const float* b1    = (const float*)d_in[4];
    const float* W2    = (const float*)d_in[5];
    const float* b2    = (const float*)d_in[6];
    float* out = (float*)d_out;            // [0,1024): relation_scores; then context

    k_proj<<<128, 256>>>(emb, geom, utter, W1, b1, W2);
    {
        dim3 g(NN/64, NN/64, BB);
        k_gemm<<<g, 256>>>();
    }
    k_soft<<<ROWS, 128>>>(b2, out);
    {
        dim3 g(4, 16, BB);
        k_ctx<<<g, 256>>>(out + ROWS);
    }
}

// round 9
// speedup vs baseline: 1.2436x; 1.2436x over previous
#include <cuda_runtime.h>

#define BB   2
#define NN   512
#define OBJ  320
#define GEO  6
#define LANG 256
#define HID  256
#define ROWS (BB*NN)   // 1024

#define C2 0.3989423f
#define C4 -0.0664904f
#define TWO_C2 0.79788456f

typedef unsigned long long u64;

__device__ __forceinline__ u64 pk2(float lo, float hi) {
    u64 r; asm("mov.b64 %0, {%1, %2};" : "=l"(r) : "f"(lo), "f"(hi)); return r;
}
__device__ __forceinline__ void upk2(float& lo, float& hi, u64 v) {
    asm("mov.b64 {%0, %1}, %2;" : "=f"(lo), "=f"(hi) : "l"(v));
}
__device__ __forceinline__ u64 ffma2(u64 a, u64 b, u64 c) {
    u64 d; asm("fma.rn.f32x2 %0, %1, %2, %3;" : "=l"(d) : "l"(a), "l"(b), "l"(c)); return d;
}

// L2-resident scratch
__device__ float g_emb[ROWS*OBJ];      // normalized embeddings
__device__ float g_hl [BB*HID];        // lang_n@Wl + b1
__device__ float g_FAt[HID*ROWS];      // [h][i]: 2*c2*W2[h]*hi[i,h]
__device__ float g_FBt[HID*ROWS];      // [h][j]: hj[j,h]
__device__ float g_Si [2*ROWS];        // per-h-half partials
__device__ float g_Sj [2*ROWS];
__device__ float g_sc [ROWS*NN];       // cross scores
__device__ float g_pw [ROWS*NN];       // softmax pair weights
__device__ float g_cp [4][ROWS*OBJ];   // context j-split partials

// ============ K0: normalize utterance, hl = lang_n@Wl + b1 ============
__global__ void __launch_bounds__(512) k_lang(const float* __restrict__ utter,
                                              const float* __restrict__ W1,
                                              const float* __restrict__ b1) {
    int b = blockIdx.x, t = threadIdx.x;   // 512 threads
    int h = t & 255, half = t >> 8;
    __shared__ float ls[LANG];
    __shared__ float red[8];
    __shared__ float part[2][HID];
    float v = 0.f;
    if (half == 0) {
        v = utter[b*LANG + t];
        float ss = v*v;
        #pragma unroll
        for (int o = 16; o; o >>= 1) ss += __shfl_xor_sync(0xffffffffu, ss, o);
        if ((t & 31) == 0) red[t >> 5] = ss;
    }
    __syncthreads();
    if (half == 0) {
        float tot = 0.f;
        #pragma unroll
        for (int w = 0; w < 8; w++) tot += red[w];
        ls[t] = v * rsqrtf(tot);
    }
    __syncthreads();
    float acc = (half == 0) ? b1[h] : 0.f;
    const float* Wl = W1 + (2*OBJ + GEO)*HID + h;
    int l0 = half * 128;
    #pragma unroll 4
    for (int l = 0; l < 128; l++) acc = fmaf(ls[l0 + l], Wl[(l0 + l)*HID], acc);
    part[half][h] = acc;
    __syncthreads();
    if (half == 0) g_hl[b*HID + h] = part[0][h] + part[1][h];
}

// ============ K1: norm + projections + features + Si/Sj partials ============
// grid 128 = 64 row-tiles (16 rows) x 2 h-halves (128 h each). 256 threads.
__global__ void __launch_bounds__(256) k_proj(const float* __restrict__ emb_raw,
                                              const float* __restrict__ geom,
                                              const float* __restrict__ W1,
                                              const float* __restrict__ W2) {
    __shared__ float e_s[16][OBJ+1];               // 20.5 KB (padded)
    __shared__ __align__(16) float2 ep[OBJ][8];    // 20 KB row-pairs
    __shared__ __align__(16) float2 gp[GEO][8];
    __shared__ float red_si[8][8], red_sj[8][8];

    int bx = blockIdx.x;
    int rowtile = bx >> 1, half = bx & 1;
    int row0 = rowtile * 16;
    int h0 = half * 128;
    int b = row0 >> 9;
    int t = threadIdx.x;
    int lane = t & 31, warp = t >> 5;
    int hh = t & 127, rp = t >> 7;                 // h-index, row-pair group
    int h = h0 + hh;

    for (int idx = t; idx < 16*OBJ; idx += 256) {
        int r = idx / OBJ, d = idx - r*OBJ;
        e_s[r][d] = emb_raw[(row0 + r)*OBJ + d];
    }
    __syncthreads();

    // normalize: warp w owns rows w and w+8
    #pragma unroll
    for (int rr = 0; rr < 2; rr++) {
        int r = warp + rr*8;
        float ss = 0.f;
        for (int d = lane; d < OBJ; d += 32) { float v = e_s[r][d]; ss = fmaf(v, v, ss); }
        #pragma unroll
        for (int o = 16; o; o >>= 1) ss += __shfl_xor_sync(0xffffffffu, ss, o);
        float inv = rsqrtf(ss);
        float* gdst = g_emb + (row0 + r)*OBJ;
        for (int d = lane; d < OBJ; d += 32) {
            float v = e_s[r][d] * inv;
            e_s[r][d] = v;
            if (half == 0) gdst[d] = v;
        }
    }
    __syncthreads();

    for (int idx = t; idx < OBJ*8; idx += 256) {
        int d = idx >> 3, p = idx & 7;
        ep[d][p] = make_float2(e_s[2*p][d], e_s[2*p+1][d]);
    }
    if (t < GEO*8) {
        int d = t >> 3, p = t & 7;
        gp[d][p] = make_float2(geom[(row0 + 2*p)*GEO + d], geom[(row0 + 2*p + 1)*GEO + d]);
    }
    __syncthreads();

    // main projection: thread handles 4 row-pairs (rp*4 .. rp*4+3) for its h
    u64 ai[4], aj[4];
    #pragma unroll
    for (int p = 0; p < 4; p++) { ai[p] = 0ull; aj[p] = 0ull; }
    const float* Wi = W1 + h;
    const float* Wj = W1 + OBJ*HID + h;
    #pragma unroll 4
    for (int d = 0; d < OBJ; d++) {
        float wi = Wi[d*HID];
        float wj = Wj[d*HID];
        u64 wip = pk2(wi, wi), wjp = pk2(wj, wj);
        ulonglong2 E01 = *(const ulonglong2*)&ep[d][rp*4];
        ulonglong2 E23 = *(const ulonglong2*)&ep[d][rp*4 + 2];
        ai[0] = ffma2(E01.x, wip, ai[0]);  aj[0] = ffma2(E01.x, wjp, aj[0]);
        ai[1] = ffma2(E01.y, wip, ai[1]);  aj[1] = ffma2(E01.y, wjp, aj[1]);
        ai[2] = ffma2(E23.x, wip, ai[2]);  aj[2] = ffma2(E23.x, wjp, aj[2]);
        ai[3] = ffma2(E23.y, wip, ai[3]);  aj[3] = ffma2(E23.y, wjp, aj[3]);
    }
    const float* Wg = W1 + 2*OBJ*HID + h;
    #pragma unroll
    for (int g = 0; g < GEO; g++) {
        float wg = Wg[g*HID];
        u64 wgp = pk2(wg, wg), wgm = pk2(-wg, -wg);
        ulonglong2 G01 = *(const ulonglong2*)&gp[g][rp*4];
        ulonglong2 G23 = *(const ulonglong2*)&gp[g][rp*4 + 2];
        ai[0] = ffma2(G01.x, wgm, ai[0]);  aj[0] = ffma2(G01.x, wgp, aj[0]);
        ai[1] = ffma2(G01.y, wgm, ai[1]);  aj[1] = ffma2(G01.y, wgp, aj[1]);
        ai[2] = ffma2(G23.x, wgm, ai[2]);  aj[2] = ffma2(G23.x, wgp, aj[2]);
        ai[3] = ffma2(G23.y, wgm, ai[3]);  aj[3] = ffma2(G23.y, wgp, aj[3]);
    }

    // epilogue: features + per-row partial reductions
    float w2v = W2[h];
    float hlv = g_hl[b*HID + h];
    float sir[8], sjr[8];
    #pragma unroll
    for (int p = 0; p < 4; p++) {
        int P = rp*4 + p;
        float a0, a1, j0v, j1v;
        upk2(a0, a1, ai[p]);
        upk2(j0v, j1v, aj[p]);
        float hv0 = a0 + hlv, hv1 = a1 + hlv;
        *(float2*)&g_FAt[h*ROWS + row0 + 2*P] = make_float2(TWO_C2*w2v*hv0, TWO_C2*w2v*hv1);
        *(float2*)&g_FBt[h*ROWS + row0 + 2*P] = make_float2(j0v, j1v);
        float u0 = hv0*hv0, u1 = hv1*hv1;
        sir[2*p]   = w2v * fmaf(u0, fmaf(C4, u0, C2), 0.5f*hv0);
        sir[2*p+1] = w2v * fmaf(u1, fmaf(C4, u1, C2), 0.5f*hv1);
        float v0 = j0v*j0v, v1 = j1v*j1v;
        sjr[2*p]   = w2v * fmaf(v0, fmaf(C4, v0, C2), 0.5f*j0v);
        sjr[2*p+1] = w2v * fmaf(v1, fmaf(C4, v1, C2), 0.5f*j1v);
    }
    #pragma unroll
    for (int lr = 0; lr < 8; lr++) {
        float si = sir[lr], sj = sjr[lr];
        #pragma unroll
        for (int o = 16; o; o >>= 1) {
            si += __shfl_xor_sync(0xffffffffu, si, o);
            sj += __shfl_xor_sync(0xffffffffu, sj, o);
        }
        if (lane == 0) { red_si[warp][lr] = si; red_sj[warp][lr] = sj; }
    }
    __syncthreads();
    if (t < 16) {
        int rpg = t >> 3, lr = t & 7;
        float v = red_si[rpg*4+0][lr] + red_si[rpg*4+1][lr]
                + red_si[rpg*4+2][lr] + red_si[rpg*4+3][lr];
        g_Si[half*ROWS + row0 + t] = v;
    } else if (t < 32) {
        int r = t - 16;
        int rpg = r >> 3, lr = r & 7;
        float v = red_sj[rpg*4+0][lr] + red_sj[rpg*4+1][lr]
                + red_sj[rpg*4+2][lr] + red_sj[rpg*4+3][lr];
        g_Sj[half*ROWS + row0 + r] = v;
    }
}

// ============ K2: cross GEMM  g_sc[i,j] = sum_h FAt[h,i]*FBt[h,j] ============
__global__ void __launch_bounds__(256) k_gemm() {
    __shared__ __align__(16) float2 Asp[16][64];
    __shared__ __align__(16) float  Bs [16][64];
    int t = threadIdx.x;
    int tx = t & 15, ty = t >> 4;
    int lk = t >> 4, l4 = (t & 15) * 4;
    int b  = blockIdx.z;
    int i0 = b*NN + blockIdx.y*64;
    int j0 = b*NN + blockIdx.x*64;

    const float* pa = g_FAt + lk*ROWS + i0 + l4;
    const float* pb = g_FBt + lk*ROWS + j0 + l4;

    u64 acc2[4][2];
    #pragma unroll
    for (int r = 0; r < 4; r++) { acc2[r][0] = 0ull; acc2[r][1] = 0ull; }

    float4 a4 = *(const float4*)pa;
    float4 b4 = *(const float4*)pb;

    #pragma unroll 1
    for (int ch = 0; ch < 16; ch++) {
        *(float4*)&Asp[lk][l4]     = make_float4(a4.x, a4.x, a4.y, a4.y);
        *(float4*)&Asp[lk][l4 + 2] = make_float4(a4.z, a4.z, a4.w, a4.w);
        *(float4*)&Bs[lk][l4] = b4;
        __syncthreads();
        if (ch < 15) {
            a4 = *(const float4*)(pa + (ch+1)*16*ROWS);
            b4 = *(const float4*)(pb + (ch+1)*16*ROWS);
        }
        #pragma unroll
        for (int k = 0; k < 16; k++) {
            ulonglong2 aA = *(const ulonglong2*)&Asp[k][ty*4];
            ulonglong2 aB = *(const ulonglong2*)&Asp[k][ty*4 + 2];
            ulonglong2 bP = *(const ulonglong2*)&Bs[k][tx*4];
            acc2[0][0] = ffma2(aA.x, bP.x, acc2[0][0]);
            acc2[0][1] = ffma2(aA.x, bP.y, acc2[0][1]);
            acc2[1][0] = ffma2(aA.y, bP.x, acc2[1][0]);
            acc2[1][1] = ffma2(aA.y, bP.y, acc2[1][1]);
            acc2[2][0] = ffma2(aB.x, bP.x, acc2[2][0]);
            acc2[2][1] = ffma2(aB.x, bP.y, acc2[2][1]);
            acc2[3][0] = ffma2(aB.y, bP.x, acc2[3][0]);
            acc2[3][1] = ffma2(aB.y, bP.y, acc2[3][1]);
        }
        __syncthreads();
    }

    int irow = i0 + ty*4;
    int jcol = blockIdx.x*64 + tx*4;
    #pragma unroll
    for (int r = 0; r < 4; r++) {
        float c0, c1, c2v, c3;
        upk2(c0, c1, acc2[r][0]);
        upk2(c2v, c3, acc2[r][1]);
        *(float4*)&g_sc[(irow + r)*NN + jcol] = make_float4(c0, c1, c2v, c3);
    }
}

// ============ K3: softmax + relation_scores ============
__global__ void k_soft(const float* __restrict__ b2p, float* __restrict__ out_scores) {
    int row = blockIdx.x;
    int b = row >> 9;
    int t = threadIdx.x;              // 128 threads, 4 cols each
    int lane = t & 31, warp = t >> 5;
    __shared__ float rm[4], rs[4], rss[4];

    float4 cr  = *(const float4*)&g_sc[row*NN + t*4];
    float4 j0  = *(const float4*)&g_Sj[b*NN + t*4];
    float4 j1  = *(const float4*)&g_Sj[ROWS + b*NN + t*4];
    float s0 = cr.x + j0.x + j1.x, s1 = cr.y + j0.y + j1.y;
    float s2 = cr.z + j0.z + j1.z, s3 = cr.w + j0.w + j1.w;

    float m = fmaxf(fmaxf(s0, s1), fmaxf(s2, s3));
    #pragma unroll
    for (int o = 16; o; o >>= 1) m = fmaxf(m, __shfl_xor_sync(0xffffffffu, m, o));
    if (lane == 0) rm[warp] = m;
    __syncthreads();
    m = fmaxf(fmaxf(rm[0], rm[1]), fmaxf(rm[2], rm[3]));

    float e0 = __expf(s0 - m), e1 = __expf(s1 - m), e2 = __expf(s2 - m), e3 = __expf(s3 - m);
    float se  = (e0 + e1) + (e2 + e3);
    float ses = fmaf(e0, s0, fmaf(e1, s1, fmaf(e2, s2, e3*s3)));
    #pragma unroll
    for (int o = 16; o; o >>= 1) {
        se  += __shfl_xor_sync(0xffffffffu, se,  o);
        ses += __shfl_xor_sync(0xffffffffu, ses, o);
    }
    if (lane == 0) { rs[warp] = se; rss[warp] = ses; }
    __syncthreads();
    float setot  = (rs[0]  + rs[1])  + (rs[2]  + rs[3]);
    float sestot = (rss[0] + rss[1]) + (rss[2] + rss[3]);

    float inv = __fdividef(1.f, setot);
    float4 pw = make_float4(e0*inv, e1*inv, e2*inv, e3*inv);
    *(float4*)&g_pw[row*NN + t*4] = pw;
    if (t == 0) out_scores[row] = sestot*inv + g_Si[row] + g_Si[ROWS + row] + b2p[0];
}

// ============ K4: context partials  g_cp[jh] += pw @ emb  (j-split GEMM) ============
// grid (16 = 4 d-tiles x 4 j-splits, 16 i-tiles of 64 rows) = 256 CTAs, 256 thr.
// thread: ig = t>>3 -> rows 2ig, 2ig+1;  dx = t&7 -> 10 d-cols (5 f32x2 pairs).
__global__ void __launch_bounds__(256) k_ctx() {
    __shared__ __align__(16) float e_s[32][80];    // 10 KB
    __shared__ float pw_s[64][36];                 // 9 KB, 72-float row pitch/2rows
    int t = threadIdx.x;
    int ig = t >> 3, dx = t & 7;
    int dt = blockIdx.x & 3, jh = blockIdx.x >> 2;
    int it = blockIdx.y;
    int i0 = it * 64;                  // global row
    int b  = it >> 3;
    int d0 = dt * 80;
    int dbase = dx * 10;
    int r0 = 2*ig, r1 = 2*ig + 1;

    u64 acc0[5], acc1[5];
    #pragma unroll
    for (int q = 0; q < 5; q++) { acc0[q] = 0ull; acc1[q] = 0ull; }

    #pragma unroll 1
    for (int ch = 0; ch < 4; ch++) {
        int j0 = jh*128 + ch*32;       // j within batch
        // load e tile: 32 j x 80 d
        #pragma unroll
        for (int pass = 0; pass < 5; pass++) {
            int idx = t + pass*256;    // 1280 float2
            int jr = idx / 40, dc = idx - jr*40;
            *(float2*)&e_s[jr][dc*2] =
                *(const float2*)&g_emb[(size_t)(b*NN + j0 + jr)*OBJ + d0 + dc*2];
        }
        // load pw tile: 64 i x 32 j (scalar stores into padded rows)
        {
            int pr = t >> 2, pc = (t & 3) * 8;
            float4 v0 = *(const float4*)&g_pw[(size_t)(i0 + pr)*NN + j0 + pc];
            float4 v1 = *(const float4*)&g_pw[(size_t)(i0 + pr)*NN + j0 + pc + 4];
            pw_s[pr][pc+0] = v0.x; pw_s[pr][pc+1] = v0.y;
            pw_s[pr][pc+2] = v0.z; pw_s[pr][pc+3] = v0.w;
            pw_s[pr][pc+4] = v1.x; pw_s[pr][pc+5] = v1.y;
            pw_s[pr][pc+6] = v1.z; pw_s[pr][pc+7] = v1.w;
        }
        __syncthreads();
        #pragma unroll
        for (int jk = 0; jk < 32; jk++) {
            float w0 = pw_s[r0][jk];
            float w1 = pw_s[r1][jk];
            u64 p0 = pk2(w0, w0);
            u64 p1 = pk2(w1, w1);
            #pragma unroll
            for (int q = 0; q < 5; q++) {
                u64 e2 = *(const u64*)&e_s[jk][dbase + 2*q];
                acc0[q] = ffma2(p0, e2, acc0[q]);
                acc1[q] = ffma2(p1, e2, acc1[q]);
            }
        }
        __syncthreads();
    }

    float* o0 = &g_cp[jh][(size_t)(i0 + r0)*OBJ + d0 + dbase];
    float* o1 = &g_cp[jh][(size_t)(i0 + r1)*OBJ + d0 + dbase];
    #pragma unroll
    for (int q = 0; q < 5; q++) {
        float x0, x1;
        upk2(x0, x1, acc0[q]);
        *(float2*)&o0[2*q] = make_float2(x0, x1);
        upk2(x0, x1, acc1[q]);
        *(float2*)&o1[2*q] = make_float2(x0, x1);
    }
}

// ============ K5: combine j-split partials ============
__global__ void __launch_bounds__(256) k_comb(float* __restrict__ out_ctx) {
    int idx = (blockIdx.x * 256 + threadIdx.x) * 4;      // over ROWS*OBJ floats
    float4 a = *(const float4*)&g_cp[0][idx];
    float4 b = *(const float4*)&g_cp[1][idx];
    float4 c = *(const float4*)&g_cp[2][idx];
    float4 d = *(const float4*)&g_cp[3][idx];
    *(float4*)&out_ctx[idx] = make_float4((a.x + b.x) + (c.x + d.x),
                                          (a.y + b.y) + (c.y + d.y),
                                          (a.z + b.z) + (c.z + d.z),
                                          (a.w + b.w) + (c.w + d.w));
}

extern "C" void kernel_launch(void* const* d_in, const int* in_sizes, int n_in,
                              void* d_out, int out_size) {
    (void)in_sizes; (void)n_in; (void)out_size;
    const float* emb   = (const float*)d_in[0];
    const float* geom  = (const float*)d_in[1];
    const float* utter = (const float*)d_in[2];
    const float* W1    = (const float*)d_in[3];
    const float* b1    = (const float*)d_in[4];
    const float* W2    = (const float*)d_in[5];
    const float* b2    = (const float*)d_in[6];
    float* out = (float*)d_out;            // [0,1024): relation_scores; then context

    k_lang<<<BB, 512>>>(utter, W1, b1);
    k_proj<<<128, 256>>>(emb, geom, W1, W2);
    {
        dim3 g(NN/64, NN/64, BB);
        k_gemm<<<g, 256>>>();
    }
    k_soft<<<ROWS, 128>>>(b2, out);
    {
        dim3 g(16, 16);
        k_ctx<<<g, 256>>>();
    }
    k_comb<<<(ROWS*OBJ)/1024, 256>>>(out + ROWS);
}